// round 17
// baseline (speedup 1.0000x reference)
#include <cuda_runtime.h>
#include <stdint.h>

#define D 128
#define MAX_NODES 100000
#define NSM 148
#define GBM 128
#define AST 129
#define ASZ (D * AST)

// 51.2 MB scratch for y = x_out @ W0
__device__ float g_y[MAX_NODES * D];

// ---------------------------------------------------------------------------
// helpers
// ---------------------------------------------------------------------------
// L2-only (bypass L1) 32B gather with evict-last residency hint
__device__ __forceinline__ void ldg_cg_el32B(const float* p, float4& lo, float4& hi) {
    unsigned long long x0, x1, x2, x3;
    asm volatile("ld.global.cg.L2::evict_last.v4.b64 {%0,%1,%2,%3}, [%4];"
                 : "=l"(x0), "=l"(x1), "=l"(x2), "=l"(x3) : "l"(p));
    lo.x = __uint_as_float((unsigned)x0); lo.y = __uint_as_float((unsigned)(x0 >> 32));
    lo.z = __uint_as_float((unsigned)x1); lo.w = __uint_as_float((unsigned)(x1 >> 32));
    hi.x = __uint_as_float((unsigned)x2); hi.y = __uint_as_float((unsigned)(x2 >> 32));
    hi.z = __uint_as_float((unsigned)x3); hi.w = __uint_as_float((unsigned)(x3 >> 32));
}
__device__ __forceinline__ void stg_el32B(float* p, unsigned long long x0,
                                          unsigned long long x1,
                                          unsigned long long x2,
                                          unsigned long long x3) {
    asm volatile("st.global.L2::evict_last.v4.b64 [%0], {%1,%2,%3,%4};"
                 :: "l"(p), "l"(x0), "l"(x1), "l"(x2), "l"(x3) : "memory");
}
__device__ __forceinline__ void cp_async4_ef(uint32_t smem_addr, const float* gptr,
                                             unsigned long long pol) {
    asm volatile("cp.async.ca.shared.global.L2::cache_hint [%0], [%1], 4, %2;"
                 :: "r"(smem_addr), "l"(gptr), "l"(pol));
}
__device__ __forceinline__ float edge_dot(const float4& Aa, const float4& Ab,
                                          const float4& Ba, const float4& Bb) {
    return Aa.x * Ba.x + Aa.y * Ba.y + Aa.z * Ba.z + Aa.w * Ba.w
         + Ab.x * Bb.x + Ab.y * Bb.y + Ab.z * Bb.z + Ab.w * Bb.w;
}

// ---------------------------------------------------------------------------
// Persistent GEMM (R15/16 config, unchanged): 148 CTAs x 512 thr, W in smem,
// A 128x128 double-buffered via cp.async (evict-first policy);
// thread = 4 rows x 8 cols as 16 packed f32x2 accumulators.
// ---------------------------------------------------------------------------
__global__ void __launch_bounds__(512, 1) gemm_xout_w(
    const float* __restrict__ x_out,
    const float* __restrict__ W,
    int n)
{
    extern __shared__ float smem[];
    float* Ws = smem;
    float* As = smem + D * D;

    const int tid    = threadIdx.x;
    const int bid    = blockIdx.x;
    const int ntiles = (n + GBM - 1) / GBM;

    #pragma unroll
    for (int i = tid; i < (D * D) / 4; i += 512)
        ((float4*)Ws)[i] = ((const float4*)W)[i];

    unsigned long long pol;
    asm("createpolicy.fractional.L2::evict_first.b64 %0, 1.0;" : "=l"(pol));

    uint32_t as_base;
    asm("{ .reg .u64 t; cvta.to.shared.u64 t, %1; cvt.u32.u64 %0, t; }"
        : "=r"(as_base) : "l"(As));

    const int kS = tid & 127;
    const int rS = tid >> 7;

    if (bid < ntiles) {
        #pragma unroll
        for (int p = 0; p < 32; p++) {
            int rr = p * 4 + rS;
            int grow = bid * GBM + rr;
            if (grow >= n) grow = n - 1;
            cp_async4_ef(as_base + (uint32_t)(kS * AST + rr) * 4,
                         &x_out[(size_t)grow * D + kS], pol);
        }
        asm volatile("cp.async.commit_group;");
    }

    const int lane = tid & 31;
    const int wcg  = tid >> 5;

    int buf = 0;
    for (int t = bid; t < ntiles; t += NSM) {
        bool has_next = (t + NSM) < ntiles;
        if (has_next) {
            int tn = t + NSM;
            uint32_t dstb = as_base + (uint32_t)((buf ^ 1) * ASZ) * 4;
            #pragma unroll
            for (int p = 0; p < 32; p++) {
                int rr = p * 4 + rS;
                int grow = tn * GBM + rr;
                if (grow >= n) grow = n - 1;
                cp_async4_ef(dstb + (uint32_t)(kS * AST + rr) * 4,
                             &x_out[(size_t)grow * D + kS], pol);
            }
            asm volatile("cp.async.commit_group;");
            asm volatile("cp.async.wait_group 1;");
        } else {
            asm volatile("cp.async.wait_group 0;");
        }
        __syncthreads();

        const float* A = As + buf * ASZ;
        unsigned long long acc[16];
        #pragma unroll
        for (int j = 0; j < 16; j++) acc[j] = 0ull;

        #pragma unroll 8
        for (int kk = 0; kk < D; kk++) {
            float a0 = A[kk * AST + lane];
            float a1 = A[kk * AST + lane + 32];
            float a2 = A[kk * AST + lane + 64];
            float a3 = A[kk * AST + lane + 96];
            unsigned long long aa0, aa1, aa2, aa3;
            asm("mov.b64 %0, {%1, %1};" : "=l"(aa0) : "r"(__float_as_uint(a0)));
            asm("mov.b64 %0, {%1, %1};" : "=l"(aa1) : "r"(__float_as_uint(a1)));
            asm("mov.b64 %0, {%1, %1};" : "=l"(aa2) : "r"(__float_as_uint(a2)));
            asm("mov.b64 %0, {%1, %1};" : "=l"(aa3) : "r"(__float_as_uint(a3)));
            const ulonglong2* wp = reinterpret_cast<const ulonglong2*>(&Ws[kk * D + wcg * 8]);
            ulonglong2 u0 = wp[0];
            ulonglong2 u1 = wp[1];
            asm("fma.rn.f32x2 %0, %1, %2, %0;" : "+l"(acc[0])  : "l"(aa0), "l"(u0.x));
            asm("fma.rn.f32x2 %0, %1, %2, %0;" : "+l"(acc[1])  : "l"(aa0), "l"(u0.y));
            asm("fma.rn.f32x2 %0, %1, %2, %0;" : "+l"(acc[2])  : "l"(aa0), "l"(u1.x));
            asm("fma.rn.f32x2 %0, %1, %2, %0;" : "+l"(acc[3])  : "l"(aa0), "l"(u1.y));
            asm("fma.rn.f32x2 %0, %1, %2, %0;" : "+l"(acc[4])  : "l"(aa1), "l"(u0.x));
            asm("fma.rn.f32x2 %0, %1, %2, %0;" : "+l"(acc[5])  : "l"(aa1), "l"(u0.y));
            asm("fma.rn.f32x2 %0, %1, %2, %0;" : "+l"(acc[6])  : "l"(aa1), "l"(u1.x));
            asm("fma.rn.f32x2 %0, %1, %2, %0;" : "+l"(acc[7])  : "l"(aa1), "l"(u1.y));
            asm("fma.rn.f32x2 %0, %1, %2, %0;" : "+l"(acc[8])  : "l"(aa2), "l"(u0.x));
            asm("fma.rn.f32x2 %0, %1, %2, %0;" : "+l"(acc[9])  : "l"(aa2), "l"(u0.y));
            asm("fma.rn.f32x2 %0, %1, %2, %0;" : "+l"(acc[10]) : "l"(aa2), "l"(u1.x));
            asm("fma.rn.f32x2 %0, %1, %2, %0;" : "+l"(acc[11]) : "l"(aa2), "l"(u1.y));
            asm("fma.rn.f32x2 %0, %1, %2, %0;" : "+l"(acc[12]) : "l"(aa3), "l"(u0.x));
            asm("fma.rn.f32x2 %0, %1, %2, %0;" : "+l"(acc[13]) : "l"(aa3), "l"(u0.y));
            asm("fma.rn.f32x2 %0, %1, %2, %0;" : "+l"(acc[14]) : "l"(aa3), "l"(u1.x));
            asm("fma.rn.f32x2 %0, %1, %2, %0;" : "+l"(acc[15]) : "l"(aa3), "l"(u1.y));
        }

        #pragma unroll
        for (int q = 0; q < 4; q++) {
            int gr = t * GBM + lane + q * 32;
            if (gr < n) {
                float* dst = g_y + (size_t)gr * D + wcg * 8;
                stg_el32B(dst, acc[q * 4 + 0], acc[q * 4 + 1],
                               acc[q * 4 + 2], acc[q * 4 + 3]);
            }
        }

        __syncthreads();
        buf ^= 1;
    }
}

// ---------------------------------------------------------------------------
// Edge kernel: warp = 8 edges. Each 16-lane group handles 4 consecutive
// edges; all 8 gathers issued before any use (MLP 8/thread). Vector index
// loads (int4 / 2x longlong2); one aligned v4 output store per group.
// ---------------------------------------------------------------------------
__global__ void __launch_bounds__(256) edge_bilinear(
    const float* __restrict__ x_in,
    const void* __restrict__ ei,
    float* __restrict__ out,
    int E)
{
    const uint4 h0 = __ldg((const uint4*)ei);
    const uint4 h1 = __ldg((const uint4*)ei + 1);
    const bool is32 = ((h0.y | h0.w | h1.y | h1.w) != 0u);

    const unsigned int gthread = blockIdx.x * blockDim.x + threadIdx.x;
    const int warp_id = (int)(gthread >> 5);
    const int lane = threadIdx.x & 31;
    const int half = lane >> 4;
    const int sub  = lane & 15;
    const int e0   = warp_id * 8 + half * 4;     // group handles e0..e0+3
    if (e0 >= E) return;
    const bool full = (e0 + 3 < E);

    long long s[4], d[4];
    if (is32) {
        const int* p = (const int*)ei;
        if (full) {
            int4 sv = __ldcs((const int4*)(p + e0));
            int4 dv = __ldcs((const int4*)(p + E + e0));
            s[0] = sv.x; s[1] = sv.y; s[2] = sv.z; s[3] = sv.w;
            d[0] = dv.x; d[1] = dv.y; d[2] = dv.z; d[3] = dv.w;
        } else {
            #pragma unroll
            for (int j = 0; j < 4; j++) {
                int e = e0 + j < E ? e0 + j : E - 1;
                s[j] = __ldcs(&p[e]);
                d[j] = __ldcs(&p[E + e]);
            }
        }
    } else {
        const long long* p = (const long long*)ei;
        if (full) {
            longlong2 sv0 = __ldcs((const longlong2*)(p + e0));
            longlong2 sv1 = __ldcs((const longlong2*)(p + e0 + 2));
            longlong2 dv0 = __ldcs((const longlong2*)(p + (long long)E + e0));
            longlong2 dv1 = __ldcs((const longlong2*)(p + (long long)E + e0 + 2));
            s[0] = sv0.x; s[1] = sv0.y; s[2] = sv1.x; s[3] = sv1.y;
            d[0] = dv0.x; d[1] = dv0.y; d[2] = dv1.x; d[3] = dv1.y;
        } else {
            #pragma unroll
            for (int j = 0; j < 4; j++) {
                long long e = e0 + j < E ? e0 + j : E - 1;
                s[j] = __ldcs(&p[e]);
                d[j] = __ldcs(&p[(long long)E + e]);
            }
        }
    }

    // issue all 8 gathers before any use
    float4 Aa[4], Ab[4], Ba[4], Bb[4];
    #pragma unroll
    for (int j = 0; j < 4; j++) {
        ldg_cg_el32B(g_y  + s[j] * D + sub * 8, Aa[j], Ab[j]);
        ldg_cg_el32B(x_in + d[j] * D + sub * 8, Ba[j], Bb[j]);
    }

    float v0 = edge_dot(Aa[0], Ab[0], Ba[0], Bb[0]);
    float v1 = edge_dot(Aa[1], Ab[1], Ba[1], Bb[1]);
    float v2 = edge_dot(Aa[2], Ab[2], Ba[2], Bb[2]);
    float v3 = edge_dot(Aa[3], Ab[3], Ba[3], Bb[3]);

    #pragma unroll
    for (int o = 8; o > 0; o >>= 1) {
        v0 += __shfl_xor_sync(0xFFFFFFFFu, v0, o);
        v1 += __shfl_xor_sync(0xFFFFFFFFu, v1, o);
        v2 += __shfl_xor_sync(0xFFFFFFFFu, v2, o);
        v3 += __shfl_xor_sync(0xFFFFFFFFu, v3, o);
    }

    if (sub == 0) {
        float r0 = 1.0f / (1.0f + __expf(-v0));
        float r1 = 1.0f / (1.0f + __expf(-v1));
        float r2 = 1.0f / (1.0f + __expf(-v2));
        float r3 = 1.0f / (1.0f + __expf(-v3));
        if (full) {
            float4 r = make_float4(r0, r1, r2, r3);
            asm volatile("st.global.cs.v4.f32 [%0], {%1,%2,%3,%4};"
                         :: "l"(&out[e0]), "f"(r.x), "f"(r.y), "f"(r.z), "f"(r.w)
                         : "memory");
        } else {
            if (e0     < E) __stcs(&out[e0],     r0);
            if (e0 + 1 < E) __stcs(&out[e0 + 1], r1);
            if (e0 + 2 < E) __stcs(&out[e0 + 2], r2);
            if (e0 + 3 < E) __stcs(&out[e0 + 3], r3);
        }
    }
}

// ---------------------------------------------------------------------------
// Launch
// ---------------------------------------------------------------------------
#define GEMM_SMEM ((D * D + 2 * ASZ) * sizeof(float))

extern "C" void kernel_launch(void* const* d_in, const int* in_sizes, int n_in,
                              void* d_out, int out_size)
{
    int i_xin = 0, i_xout = 1, i_ei = 2, i_w = 3;

    if (n_in == 4) {
        int w_idx = -1, ei_idx = -1;
        for (int i = 0; i < 4; i++)
            if (in_sizes[i] == D * D) w_idx = i;
        int idx[3], c = 0;
        for (int i = 0; i < 4; i++) if (i != w_idx) idx[c++] = i;
        if (w_idx >= 0 && c == 3) {
            if (in_sizes[idx[0]] == in_sizes[idx[1]])      { i_xin = idx[0]; i_xout = idx[1]; ei_idx = idx[2]; }
            else if (in_sizes[idx[0]] == in_sizes[idx[2]]) { i_xin = idx[0]; i_xout = idx[2]; ei_idx = idx[1]; }
            else                                            { i_xin = idx[1]; i_xout = idx[2]; ei_idx = idx[0]; }
            i_w = w_idx; i_ei = ei_idx;
        }
    }

    const float* x_in  = (const float*)d_in[i_xin];
    const float* x_out = (const float*)d_in[i_xout];
    const void*  ei    = d_in[i_ei];
    const float* W     = (const float*)d_in[i_w];
    float*       out   = (float*)d_out;

    int n = in_sizes[i_xin] / D;
    if (n > MAX_NODES) n = MAX_NODES;
    int E = in_sizes[i_ei] / 2;

    static int smem_set = 0;
    if (!smem_set) {
        cudaFuncSetAttribute(gemm_xout_w, cudaFuncAttributeMaxDynamicSharedMemorySize,
                             (int)GEMM_SMEM);
        smem_set = 1;
    }

    gemm_xout_w<<<NSM, 512, GEMM_SMEM>>>(x_out, W, n);

    {
        // one warp per 8 edges
        long long warps = ((long long)E + 7) / 8;
        long long total_threads = warps * 32;
        int blocks = (int)((total_threads + 255) / 256);
        edge_bilinear<<<blocks, 256>>>(x_in, ei, out, E);
    }
}